// round 15
// baseline (speedup 1.0000x reference)
#include <cuda_runtime.h>
#include <math.h>

#define BSZ   65536
#define SEQ   25
#define HID   64
#define ACT   4
#define TSTEP 16
#define BETA  0.95f
#define THRV  1.0f
#define ELIG_DECAY 0.95f
#define ELIG_C     (-0.002f)    // A_PLUS - A_MINUS

#define NBLK  148               // 1 block per SM, single wave
#define WPB   20                // warps per block (640 threads, 102-reg budget)
#define NTHR  640
// quads: 4 rows each; 2960 warps; 1584 warps x 6 quads + 1376 x 5 = 16384 quads
#define QUADS_BIG 1584

#define W3_SCALE     8388608.0f          // 2^23 (exact integer reduction)
#define W3_INV_SCALE (1.0f / 8388608.0f)

// ---- aligned-region byte offsets (from 16KB-aligned base "ab") ----
// tbl6  : 10 groups x 64 pat x 16 lanes x float4 = 163840 (group g at g*16384)
// tbl4  : 16 pat x 16 lanes x float4             =   4096 (at 163840)
// w1t4  : 25 x 16 x float4                       =   6400 (at 167936)
// b1s   : 16 x float4                            =    256 (at 174336)
// bank2 : u32[2][20][16][8]                      =  20480 (at 174592)
// bank3 : u32[2][20][4][2]                       =   1280 (at 195072)
// flag  : 4                                         (at 196352)
#define OFF_TBL4  163840
#define OFF_W1T   167936
#define OFF_B1S   174336
#define OFF_BANK2 174592
#define OFF_BANK3 195072
#define OFF_FLAG  196352
#define SMEM_REQ  (196480 + 16384)   // payload + alignment slack

// Graph-safe persistent scratch; last block re-zeroes everything each call.
__device__ float    g_s2sum[TSTEP * HID];
__device__ float    g_s3sum[TSTEP * ACT];
__device__ unsigned g_ctr;

// W2 LUT lookup serving a 2-row pair: v has the pattern pre-shifted to bits
// [8,14) (different per half-warp). addr = (v & MASK) | tb_lane via one LOP3.
// LDS.128 fetches float4 = 4 neuron-classes for this lane's row.
template <int IMM, unsigned MASK>
__device__ __forceinline__ void lutW2(unsigned v, unsigned tb_lane,
                                      unsigned long long& acc01,
                                      unsigned long long& acc23) {
    unsigned addr;
    asm("lop3.b32 %0, %1, %2, %3, 0xEA;"
        : "=r"(addr) : "r"(v), "n"(MASK), "r"(tb_lane));
    unsigned long long w01, w23;
    asm("ld.shared.v2.b64 {%0, %1}, [%2+%3];"
        : "=l"(w01), "=l"(w23) : "r"(addr), "n"(IMM));
    asm("add.rn.f32x2 %0, %0, %1;" : "+l"(acc01) : "l"(w01));
    asm("add.rn.f32x2 %0, %0, %1;" : "+l"(acc23) : "l"(w23));
}

// Full 64-neuron masked W2 column sums for one pair-unit -> a0..a3
__device__ __forceinline__ void w2_pair(unsigned ma, unsigned mb,
                                        unsigned tb_lane,
                                        unsigned long long b2p01,
                                        unsigned long long b2p23,
                                        float& a0, float& a1,
                                        float& a2, float& a3) {
    unsigned long long s0a = b2p01, s0b = b2p23;
    unsigned long long s1a = 0, s1b = 0, s2a = 0, s2b = 0;
    lutW2<0 * 16384, 0x3F00u>(ma << 8,  tb_lane, s0a, s0b);
    lutW2<1 * 16384, 0x3F00u>(ma << 2,  tb_lane, s1a, s1b);
    lutW2<2 * 16384, 0x3F00u>(ma >> 4,  tb_lane, s2a, s2b);
    lutW2<3 * 16384, 0x3F00u>(ma >> 10, tb_lane, s0a, s0b);
    lutW2<4 * 16384, 0x3F00u>(ma >> 16, tb_lane, s1a, s1b);
    lutW2<5 * 16384, 0x3F00u>(__funnelshift_r(ma, mb, 22), tb_lane, s2a, s2b);
    lutW2<6 * 16384, 0x3F00u>(mb << 4,  tb_lane, s0a, s0b);
    lutW2<7 * 16384, 0x3F00u>(mb >> 2,  tb_lane, s1a, s1b);
    lutW2<8 * 16384, 0x3F00u>(mb >> 8,  tb_lane, s2a, s2b);
    lutW2<9 * 16384, 0x3F00u>(mb >> 14, tb_lane, s0a, s0b);
    lutW2<OFF_TBL4,  0x0F00u>(mb >> 20, tb_lane, s1a, s1b);
    asm("add.rn.f32x2 %0, %0, %1;" : "+l"(s0a) : "l"(s1a));
    asm("add.rn.f32x2 %0, %0, %1;" : "+l"(s0b) : "l"(s1b));
    asm("add.rn.f32x2 %0, %0, %1;" : "+l"(s0a) : "l"(s2a));
    asm("add.rn.f32x2 %0, %0, %1;" : "+l"(s0b) : "l"(s2b));
    asm("mov.b64 {%0, %1}, %2;" : "=f"(a0), "=f"(a1) : "l"(s0a));
    asm("mov.b64 {%0, %1}, %2;" : "=f"(a2), "=f"(a3) : "l"(s0b));
}

// ---------------------------------------------------------------------------
// Fused kernel. Each warp processes a QUAD (4 rows) as two interleaved
// independent pair-units. Within a unit, lanes 0-15 = row h0, 16-31 = row h1;
// lane (h, hl) owns neurons hl, hl+16, hl+32, hl+48 of its row.
// Layer 3: exact integer partials + half-warp __reduce_add_sync.
// ---------------------------------------------------------------------------
__global__ void __launch_bounds__(NTHR, 1) snn_main(
    const float* __restrict__ x,   // [B, 25]
    const float* __restrict__ W1,  // [64, 25]
    const float* __restrict__ b1,  // [64]
    const float* __restrict__ W2,  // [64, 64]
    const float* __restrict__ b2,  // [64]
    const float* __restrict__ W3,  // [4, 64]
    const float* __restrict__ b3,  // [4]
    const float* __restrict__ elig0,
    float* __restrict__ out, int elig_off)
{
    extern __shared__ unsigned char smem_raw[];
    const unsigned dyn = (unsigned)__cvta_generic_to_shared(smem_raw);
    const unsigned ab  = (dyn + 16383u) & 0xFFFFC000u;   // 16KB-aligned base
    unsigned char* base = smem_raw + (ab - dyn);

    const int tid  = threadIdx.x;
    const int lane = tid & 31;
    const int warp = tid >> 5;

    // ---- build float4 W2 LUTs (entry[g][pat][hl] = neurons hl+16c) ----
    if (tid < 160) {
        const int g = tid >> 4, hl = tid & 15;
        float w[4][6];
        #pragma unroll
        for (int c = 0; c < 4; c++)
            #pragma unroll
            for (int b = 0; b < 6; b++)
                w[c][b] = W2[(hl + 16 * c) * HID + 6 * g + b];
        float4* tg = (float4*)(base + g * 16384) + hl;    // pattern stride 16 f4
        tg[0] = make_float4(0.f, 0.f, 0.f, 0.f);
        for (int n = 1; n < 64; n++) {
            int b = __ffs(n) - 1;
            float4 p = tg[(n & (n - 1)) * 16];
            tg[n * 16] = make_float4(p.x + w[0][b], p.y + w[1][b],
                                     p.z + w[2][b], p.w + w[3][b]);
        }
    } else if (tid < 176) {
        const int hl = tid - 160;
        float w[4][4];
        #pragma unroll
        for (int c = 0; c < 4; c++)
            #pragma unroll
            for (int b = 0; b < 4; b++)
                w[c][b] = W2[(hl + 16 * c) * HID + 60 + b];
        float4* tg = (float4*)(base + OFF_TBL4) + hl;
        tg[0] = make_float4(0.f, 0.f, 0.f, 0.f);
        for (int n = 1; n < 16; n++) {
            int b = __ffs(n) - 1;
            float4 p = tg[(n & (n - 1)) * 16];
            tg[n * 16] = make_float4(p.x + w[0][b], p.y + w[1][b],
                                     p.z + w[2][b], p.w + w[3][b]);
        }
    }
    // ---- stage W1 transposed (float4) + b1 ----
    {
        float4* w1t = (float4*)(base + OFF_W1T);
        for (int idx = tid; idx < SEQ * 16; idx += NTHR) {
            int k = idx >> 4, hl = idx & 15;
            w1t[k * 16 + hl] = make_float4(
                W1[hl * SEQ + k], W1[(hl + 16) * SEQ + k],
                W1[(hl + 32) * SEQ + k], W1[(hl + 48) * SEQ + k]);
        }
        if (tid < 16)
            ((float4*)(base + OFF_B1S))[tid] =
                make_float4(b1[tid], b1[tid + 16], b1[tid + 32], b1[tid + 48]);
    }
    __syncthreads();

    const int h  = lane >> 4;          // which row of each pair
    const int hl = lane & 15;
    const int a3 = lane & 3;           // action owned by this lane
    const bool lb0 = (lane & 1) != 0, lb1 = (lane & 2) != 0;

    const float b3me = b3[a3];
    unsigned long long b2p01, b2p23;
    {
        float v0 = b2[hl], v1 = b2[hl + 16], v2 = b2[hl + 32], v3 = b2[hl + 48];
        asm("mov.b64 %0, {%1, %2};" : "=l"(b2p01) : "f"(v0), "f"(v1));
        asm("mov.b64 %0, {%1, %2};" : "=l"(b2p23) : "f"(v2), "f"(v3));
    }
    int w3q[4][4];                     // [action][neuron-class]
    #pragma unroll
    for (int a = 0; a < 4; a++)
        #pragma unroll
        for (int c = 0; c < 4; c++)
            w3q[a][c] = __float2int_rn(W3[a * HID + hl + 16 * c] * W3_SCALE);

    const unsigned sel     = h ? 0x7632u : 0x5410u;       // PRMT mask assembly
    const unsigned hmask   = h ? 0xFFFF0000u : 0x0000FFFFu;
    const unsigned tb_lane = ab + (unsigned)hl * 16u;     // bits [13:8] = 0
    const float4 b1v = ((const float4*)(base + OFF_B1S))[hl];

    // spike counters (nibbles; <=12 per segment after half-merge)
    unsigned c2r[8] = {0, 0, 0, 0, 0, 0, 0, 0};   // [class][t-half]
    unsigned cme_lo = 0u, cme_hi = 0u;            // own action

    const int gwarp = blockIdx.x * WPB + warp;
    const int quad0 = gwarp * 5 + min(gwarp, QUADS_BIG);
    const int nq    = 5 + (gwarp < QUADS_BIG ? 1 : 0);

    const float4* w1t = (const float4*)(base + OFF_W1T);
    unsigned* bank2 = (unsigned*)(base + OFF_BANK2);
    unsigned* bank3 = (unsigned*)(base + OFF_BANK3);
    int seg = 0;

    for (int q = 0; q < nq; q++) {
        const int rowA = (quad0 + q) * 4 + h;        // unit A: rows +0/+1
        const int rowB = rowA + 2;                   // unit B: rows +2/+3

        // ---- cur = x[row] @ W1^T + b1 for both units ----
        const float* xrA = x + rowA * SEQ;
        const float* xrB = x + rowB * SEQ;
        float xaA = xrA[hl], xbA = (hl < 9) ? xrA[16 + hl] : 0.0f;
        float xaB = xrB[hl], xbB = (hl < 9) ? xrB[16 + hl] : 0.0f;
        float cA0 = b1v.x, cA1 = b1v.y, cA2 = b1v.z, cA3 = b1v.w;
        float cB0 = b1v.x, cB1 = b1v.y, cB2 = b1v.z, cB3 = b1v.w;
        #pragma unroll
        for (int k = 0; k < SEQ; k++) {
            float xvA = __shfl_sync(0xffffffffu, (k < 16) ? xaA : xbA,
                                    (lane & 16) | (k & 15));
            float xvB = __shfl_sync(0xffffffffu, (k < 16) ? xaB : xbB,
                                    (lane & 16) | (k & 15));
            float4 wv = w1t[k * 16 + hl];
            cA0 = fmaf(xvA, wv.x, cA0); cA1 = fmaf(xvA, wv.y, cA1);
            cA2 = fmaf(xvA, wv.z, cA2); cA3 = fmaf(xvA, wv.w, cA3);
            cB0 = fmaf(xvB, wv.x, cB0); cB1 = fmaf(xvB, wv.y, cB1);
            cB2 = fmaf(xvB, wv.z, cB2); cB3 = fmaf(xvB, wv.w, cB3);
        }

        float mA1_0 = 0.f, mA1_1 = 0.f, mA1_2 = 0.f, mA1_3 = 0.f;
        float mA2_0 = 0.f, mA2_1 = 0.f, mA2_2 = 0.f, mA2_3 = 0.f;
        float mB1_0 = 0.f, mB1_1 = 0.f, mB1_2 = 0.f, mB1_3 = 0.f;
        float mB2_0 = 0.f, mB2_1 = 0.f, mB2_2 = 0.f, mB2_3 = 0.f;
        float m3A = 0.f, acA = 0.f, m3B = 0.f, acB = 0.f;

        #pragma unroll
        for (int tp = 0; tp < 2; tp++) {
            #pragma unroll 1
            for (int tt = 0; tt < 8; tt++) {
                const unsigned nib = 1u << (tt * 4);

                // ---- layer 1, both units ----
                mA1_0 = fmaf(BETA, mA1_0, cA0);
                mA1_1 = fmaf(BETA, mA1_1, cA1);
                mA1_2 = fmaf(BETA, mA1_2, cA2);
                mA1_3 = fmaf(BETA, mA1_3, cA3);
                mB1_0 = fmaf(BETA, mB1_0, cB0);
                mB1_1 = fmaf(BETA, mB1_1, cB1);
                mB1_2 = fmaf(BETA, mB1_2, cB2);
                mB1_3 = fmaf(BETA, mB1_3, cB3);
                bool fA0 = mA1_0 > THRV, fA1 = mA1_1 > THRV;
                bool fA2 = mA1_2 > THRV, fA3 = mA1_3 > THRV;
                bool fB0 = mB1_0 > THRV, fB1 = mB1_1 > THRV;
                bool fB2 = mB1_2 > THRV, fB3 = mB1_3 > THRV;
                if (fA0) mA1_0 -= THRV;
                if (fA1) mA1_1 -= THRV;
                if (fA2) mA1_2 -= THRV;
                if (fA3) mA1_3 -= THRV;
                if (fB0) mB1_0 -= THRV;
                if (fB1) mB1_1 -= THRV;
                if (fB2) mB1_2 -= THRV;
                if (fB3) mB1_3 -= THRV;
                unsigned aA0 = __ballot_sync(0xffffffffu, fA0);
                unsigned aA1 = __ballot_sync(0xffffffffu, fA1);
                unsigned aA2 = __ballot_sync(0xffffffffu, fA2);
                unsigned aA3 = __ballot_sync(0xffffffffu, fA3);
                unsigned aB0 = __ballot_sync(0xffffffffu, fB0);
                unsigned aB1 = __ballot_sync(0xffffffffu, fB1);
                unsigned aB2 = __ballot_sync(0xffffffffu, fB2);
                unsigned aB3 = __ballot_sync(0xffffffffu, fB3);
                unsigned maA = __byte_perm(aA0, aA1, sel);
                unsigned mbA = __byte_perm(aA2, aA3, sel);
                unsigned maB = __byte_perm(aB0, aB1, sel);
                unsigned mbB = __byte_perm(aB2, aB3, sel);

                // ---- layer 2: 22 LDS.128 lookups (2 independent chains) ----
                float vA0, vA1, vA2, vA3, vB0, vB1, vB2, vB3;
                w2_pair(maA, mbA, tb_lane, b2p01, b2p23, vA0, vA1, vA2, vA3);
                w2_pair(maB, mbB, tb_lane, b2p01, b2p23, vB0, vB1, vB2, vB3);

                mA2_0 = fmaf(BETA, mA2_0, vA0);
                mA2_1 = fmaf(BETA, mA2_1, vA1);
                mA2_2 = fmaf(BETA, mA2_2, vA2);
                mA2_3 = fmaf(BETA, mA2_3, vA3);
                mB2_0 = fmaf(BETA, mB2_0, vB0);
                mB2_1 = fmaf(BETA, mB2_1, vB1);
                mB2_2 = fmaf(BETA, mB2_2, vB2);
                mB2_3 = fmaf(BETA, mB2_3, vB3);
                bool qA0 = mA2_0 > THRV, qA1 = mA2_1 > THRV;
                bool qA2 = mA2_2 > THRV, qA3 = mA2_3 > THRV;
                bool qB0 = mB2_0 > THRV, qB1 = mB2_1 > THRV;
                bool qB2 = mB2_2 > THRV, qB3 = mB2_3 > THRV;
                if (qA0) mA2_0 -= THRV;
                if (qA1) mA2_1 -= THRV;
                if (qA2) mA2_2 -= THRV;
                if (qA3) mA2_3 -= THRV;
                if (qB0) mB2_0 -= THRV;
                if (qB1) mB2_1 -= THRV;
                if (qB2) mB2_2 -= THRV;
                if (qB3) mB2_3 -= THRV;

                // s2 nibble counters (<=2 per t)
                c2r[0 * 2 + tp] += (qA0 ? nib : 0u) + (qB0 ? nib : 0u);
                c2r[1 * 2 + tp] += (qA1 ? nib : 0u) + (qB1 ? nib : 0u);
                c2r[2 * 2 + tp] += (qA2 ? nib : 0u) + (qB2 ? nib : 0u);
                c2r[3 * 2 + tp] += (qA3 ? nib : 0u) + (qB3 ? nib : 0u);

                // ---- layer 3: integer partials + half-warp reduxes ----
                int sA0 = qA0 ? 1 : 0, sA1 = qA1 ? 1 : 0;
                int sA2 = qA2 ? 1 : 0, sA3 = qA3 ? 1 : 0;
                int sB0 = qB0 ? 1 : 0, sB1 = qB1 ? 1 : 0;
                int sB2 = qB2 ? 1 : 0, sB3 = qB3 ? 1 : 0;
                int pA0 = sA0 * w3q[0][0] + sA1 * w3q[0][1] + sA2 * w3q[0][2] + sA3 * w3q[0][3];
                int pA1 = sA0 * w3q[1][0] + sA1 * w3q[1][1] + sA2 * w3q[1][2] + sA3 * w3q[1][3];
                int pA2 = sA0 * w3q[2][0] + sA1 * w3q[2][1] + sA2 * w3q[2][2] + sA3 * w3q[2][3];
                int pA3 = sA0 * w3q[3][0] + sA1 * w3q[3][1] + sA2 * w3q[3][2] + sA3 * w3q[3][3];
                int pB0 = sB0 * w3q[0][0] + sB1 * w3q[0][1] + sB2 * w3q[0][2] + sB3 * w3q[0][3];
                int pB1 = sB0 * w3q[1][0] + sB1 * w3q[1][1] + sB2 * w3q[1][2] + sB3 * w3q[1][3];
                int pB2 = sB0 * w3q[2][0] + sB1 * w3q[2][1] + sB2 * w3q[2][2] + sB3 * w3q[2][3];
                int pB3 = sB0 * w3q[3][0] + sB1 * w3q[3][1] + sB2 * w3q[3][2] + sB3 * w3q[3][3];
                pA0 = __reduce_add_sync(hmask, pA0);
                pA1 = __reduce_add_sync(hmask, pA1);
                pA2 = __reduce_add_sync(hmask, pA2);
                pA3 = __reduce_add_sync(hmask, pA3);
                pB0 = __reduce_add_sync(hmask, pB0);
                pB1 = __reduce_add_sync(hmask, pB1);
                pB2 = __reduce_add_sync(hmask, pB2);
                pB3 = __reduce_add_sync(hmask, pB3);

                int pmA = lb1 ? (lb0 ? pA3 : pA2) : (lb0 ? pA1 : pA0);
                int pmB = lb1 ? (lb0 ? pB3 : pB2) : (lb0 ? pB1 : pB0);
                float pfA = fmaf((float)pmA, W3_INV_SCALE, b3me);
                float pfB = fmaf((float)pmB, W3_INV_SCALE, b3me);
                m3A = fmaf(BETA, m3A, pfA);
                m3B = fmaf(BETA, m3B, pfB);
                bool gA = m3A > THRV, gB = m3B > THRV;
                if (gA) { m3A -= THRV; acA += 1.0f; }
                if (gB) { m3B -= THRV; acB += 1.0f; }
                unsigned add3 = (gA ? nib : 0u) + (gB ? nib : 0u);
                if (tp == 0) cme_lo += add3;
                else         cme_hi += add3;
            }
        }

        // ---- softmax(acc / T), both units (hl==0 of each half writes) ----
        float gA0 = __shfl_sync(0xffffffffu, acA, (lane & 16) | 0);
        float gA1 = __shfl_sync(0xffffffffu, acA, (lane & 16) | 1);
        float gA2 = __shfl_sync(0xffffffffu, acA, (lane & 16) | 2);
        float gA3 = __shfl_sync(0xffffffffu, acA, (lane & 16) | 3);
        float gB0 = __shfl_sync(0xffffffffu, acB, (lane & 16) | 0);
        float gB1 = __shfl_sync(0xffffffffu, acB, (lane & 16) | 1);
        float gB2 = __shfl_sync(0xffffffffu, acB, (lane & 16) | 2);
        float gB3 = __shfl_sync(0xffffffffu, acB, (lane & 16) | 3);
        if (hl == 0) {
            const float invT = 1.0f / (float)TSTEP;
            {
                float r0 = gA0 * invT, r1 = gA1 * invT;
                float r2 = gA2 * invT, r3 = gA3 * invT;
                float mx = fmaxf(fmaxf(r0, r1), fmaxf(r2, r3));
                float e0 = __expf(r0 - mx), e1 = __expf(r1 - mx);
                float e2 = __expf(r2 - mx), e3 = __expf(r3 - mx);
                float rs = __fdividef(1.0f, e0 + e1 + e2 + e3);
                *reinterpret_cast<float4*>(out + (size_t)rowA * ACT) =
                    make_float4(e0 * rs, e1 * rs, e2 * rs, e3 * rs);
            }
            {
                float r0 = gB0 * invT, r1 = gB1 * invT;
                float r2 = gB2 * invT, r3 = gB3 * invT;
                float mx = fmaxf(fmaxf(r0, r1), fmaxf(r2, r3));
                float e0 = __expf(r0 - mx), e1 = __expf(r1 - mx);
                float e2 = __expf(r2 - mx), e3 = __expf(r3 - mx);
                float rs = __fdividef(1.0f, e0 + e1 + e2 + e3);
                *reinterpret_cast<float4*>(out + (size_t)rowB * ACT) =
                    make_float4(e0 * rs, e1 * rs, e2 * rs, e3 * rs);
            }
        }

        // ---- segment flush after quad 2 and at the last quad ----
        if (q == 2 || q == nq - 1) {
            #pragma unroll
            for (int i = 0; i < 8; i++)
                c2r[i] += __shfl_down_sync(0xffffffffu, c2r[i], 16);
            cme_lo += __shfl_down_sync(0xffffffffu, cme_lo, 16);
            cme_hi += __shfl_down_sync(0xffffffffu, cme_hi, 16);
            if (h == 0) {
                unsigned* d2 = bank2 + (((seg * WPB + warp) * 16) + hl) * 8;
                *reinterpret_cast<uint4*>(d2) =
                    make_uint4(c2r[0], c2r[1], c2r[2], c2r[3]);
                *reinterpret_cast<uint4*>(d2 + 4) =
                    make_uint4(c2r[4], c2r[5], c2r[6], c2r[7]);
                if (hl < 4) {
                    unsigned* d3 = bank3 + ((seg * WPB + warp) * 4 + hl) * 2;
                    d3[0] = cme_lo;
                    d3[1] = cme_hi;
                }
            }
            #pragma unroll
            for (int i = 0; i < 8; i++) c2r[i] = 0u;
            cme_lo = cme_hi = 0u;
            seg++;
        }
    }

    // ---- final sweep: sum banks -> global atomics ----
    __syncthreads();
    for (int c = tid; c < TSTEP * HID; c += NTHR) {
        int t = c >> 6, j = c & 63;
        int hlp = j & 15, cls = j >> 4;
        int reg = cls * 2 + (t >> 3);
        int sh = (t & 7) * 4;
        unsigned cnt = 0;
        #pragma unroll
        for (int s = 0; s < 2; s++)
            for (int w = 0; w < WPB; w++)
                cnt += (bank2[(((s * WPB + w) * 16) + hlp) * 8 + reg] >> sh) & 15u;
        atomicAdd(&g_s2sum[c], (float)cnt);
    }
    if (tid < TSTEP * ACT) {
        int t = tid >> 2, a = tid & 3;
        int reg = t >> 3, sh = (t & 7) * 4;
        unsigned cnt = 0;
        #pragma unroll
        for (int s = 0; s < 2; s++)
            for (int w = 0; w < WPB; w++)
                cnt += (bank3[((s * WPB + w) * 4 + a) * 2 + reg] >> sh) & 15u;
        atomicAdd(&g_s3sum[tid], (float)cnt);
    }

    // ---- last-block: eligibility trace + reset of globals ----
    unsigned* flagp = (unsigned*)(base + OFF_FLAG);
    __threadfence();
    __syncthreads();
    if (tid == 0)
        *flagp = (atomicAdd(&g_ctr, 1u) == (unsigned)(NBLK - 1)) ? 1u : 0u;
    __syncthreads();
    if (*flagp) {
        if (tid < ACT * HID) {
            int a = tid >> 6, hh = tid & 63;
            const float invB = 1.0f / (float)BSZ;
            volatile float* s3v = g_s3sum;
            volatile float* s2v = g_s2sum;
            float e = elig0[tid];
            #pragma unroll
            for (int t = 0; t < TSTEP; t++) {
                float post = s3v[t * ACT + a] * invB;
                float pre  = s2v[t * HID + hh] * invB;
                e = ELIG_DECAY * e + ELIG_C * (post * pre);
            }
            out[elig_off + tid] = e;
        }
        __syncthreads();
        for (int i = tid; i < TSTEP * HID; i += NTHR) g_s2sum[i] = 0.0f;
        if (tid < TSTEP * ACT) g_s3sum[tid] = 0.0f;
        if (tid == 0) g_ctr = 0u;
    }
}

// ---------------------------------------------------------------------------
// Inputs (metadata order): x, W1, b1, W2, b2, W3, b3, elig0
// Output: probs [B,4] then elig [4,64] at the tail of out.
// ---------------------------------------------------------------------------
extern "C" void kernel_launch(void* const* d_in, const int* in_sizes, int n_in,
                              void* d_out, int out_size) {
    const float* x     = (const float*)d_in[0];
    const float* W1    = (const float*)d_in[1];
    const float* b1    = (const float*)d_in[2];
    const float* W2    = (const float*)d_in[3];
    const float* b2    = (const float*)d_in[4];
    const float* W3    = (const float*)d_in[5];
    const float* b3    = (const float*)d_in[6];
    const float* elig0 = (const float*)d_in[7];
    float* out = (float*)d_out;

    cudaFuncSetAttribute(snn_main, cudaFuncAttributeMaxDynamicSharedMemorySize,
                         SMEM_REQ);
    int elig_off = out_size - ACT * HID;
    snn_main<<<NBLK, NTHR, SMEM_REQ>>>(x, W1, b1, W2, b2, W3, b3,
                                       elig0, out, elig_off);
}

// round 17
// speedup vs baseline: 1.6767x; 1.6767x over previous
#include <cuda_runtime.h>
#include <math.h>

#define BSZ   65536
#define SEQ   25
#define HID   64
#define ACT   4
#define TSTEP 16
#define BETA  0.95f
#define THRV  1.0f
#define ELIG_DECAY 0.95f
#define ELIG_C     (-0.002f)    // A_PLUS - A_MINUS

#define NBLK  148               // 1 block per SM, single wave
#define WPB   24                // warps per block (768 threads, 85-reg budget)
#define NTHR  768
#define NWARP (NBLK * WPB)      // 3552 warps
// 65536 = 3552*18 + 1600 -> first 1600 warps take 19 rows, rest 18
#define WARPS_BIG 1600

#define W3_SCALE     8388608.0f          // 2^23 (exact integer reduction)
#define W3_INV_SCALE (1.0f / 8388608.0f)

// ---- aligned-region byte offsets (from 16KB-aligned base "ab") ----
// tbl6  : 10 groups x 64 pat x 32 lanes x float2 = 163840 (group g at g*16384)
// tbl4  : 16 pat x 32 lanes x float2             =   4096 (at 163840)
// w1t   : 25 x 32 x float2                       =   6400 (at 167936)
// bank2 : u32[2][24][32][4] s2 counter segments  =  24576 (at 174336)
// bank3 : u32[2][24][4][2]  s3 counter segments  =   1536 (at 198912)
// flag  : 4                                         (at 200448)
#define OFF_TBL4  163840
#define OFF_W1T   167936
#define OFF_BANK2 174336
#define OFF_BANK3 198912
#define OFF_FLAG  200448
#define SMEM_REQ  (200576 + 16384)   // payload + alignment slack

// Graph-safe persistent scratch; last block re-zeroes everything each call.
__device__ float    g_s2sum[TSTEP * HID];
__device__ float    g_s3sum[TSTEP * ACT];
__device__ unsigned g_ctr;

__device__ __forceinline__ int warp_redux_add_s32(int v) {
    int r;
    asm volatile("redux.sync.add.s32 %0, %1, 0xffffffff;" : "=r"(r) : "r"(v));
    return r;
}

// W2 LUT lookup: v has the pattern pre-shifted to bits [8,14).
// addr = (v & MASK) | tb_lane  (single LOP3, valid because tb_lane bits[13:8]=0)
template <int IMM, unsigned MASK>
__device__ __forceinline__ void lutW2(unsigned v, unsigned tb_lane,
                                      unsigned long long& acc) {
    unsigned addr;
    asm("lop3.b32 %0, %1, %2, %3, 0xEA;"
        : "=r"(addr) : "r"(v), "n"(MASK), "r"(tb_lane));
    unsigned long long w;
    asm volatile("ld.shared.b64 %0, [%1+%2];" : "=l"(w) : "r"(addr), "n"(IMM));
    asm("add.rn.f32x2 %0, %0, %1;" : "+l"(acc) : "l"(w));
}

// ---------------------------------------------------------------------------
// Fused kernel, PHASE-SPLIT: layer 1 is autonomous, so all 16 spike masks are
// computed upfront (phase 1); phase 2 runs the m2/m3 recurrence with masks
// already in registers, letting ptxas pipeline the LDS stream across
// timesteps. One warp per row (18-19 rows/warp); lane l owns neurons l, l+32.
// Layer 3: exact integer IMAD partials + 4 warp reduxes; lane l owns action l&3.
// ---------------------------------------------------------------------------
__global__ void __launch_bounds__(NTHR, 1) snn_main(
    const float* __restrict__ x,   // [B, 25]
    const float* __restrict__ W1,  // [64, 25]
    const float* __restrict__ b1,  // [64]
    const float* __restrict__ W2,  // [64, 64]
    const float* __restrict__ b2,  // [64]
    const float* __restrict__ W3,  // [4, 64]
    const float* __restrict__ b3,  // [4]
    const float* __restrict__ elig0,
    float* __restrict__ out, int elig_off)
{
    extern __shared__ unsigned char smem_raw[];
    const unsigned dyn = (unsigned)__cvta_generic_to_shared(smem_raw);
    const unsigned ab  = (dyn + 16383u) & 0xFFFFC000u;   // 16KB-aligned base
    unsigned char* base = smem_raw + (ab - dyn);

    const int tid  = threadIdx.x;
    const int lane = tid & 31;
    const int warp = tid >> 5;

    // ---- build 6-bit W2 LUT (tbl6[g][pat][lane] = float2 partial col sums) ----
    if (tid < 320) {
        const int g = tid >> 5, l = tid & 31;
        float wa[6], wb[6];
        #pragma unroll
        for (int b = 0; b < 6; b++) {
            int j = 6 * g + b;
            wa[b] = W2[l * HID + j];
            wb[b] = W2[(l + 32) * HID + j];
        }
        float2* tg = (float2*)(base + g * 16384) + l;     // stride 32 float2
        tg[0] = make_float2(0.f, 0.f);
        for (int n = 1; n < 64; n++) {
            int b = __ffs(n) - 1;
            float2 prev = tg[(n & (n - 1)) * 32];
            tg[n * 32] = make_float2(prev.x + wa[b], prev.y + wb[b]);
        }
    } else if (tid < 352) {
        const int l = tid - 320;
        float wa[4], wb[4];
        #pragma unroll
        for (int b = 0; b < 4; b++) {
            int j = 60 + b;
            wa[b] = W2[l * HID + j];
            wb[b] = W2[(l + 32) * HID + j];
        }
        float2* tg = (float2*)(base + OFF_TBL4) + l;
        tg[0] = make_float2(0.f, 0.f);
        for (int n = 1; n < 16; n++) {
            int b = __ffs(n) - 1;
            float2 prev = tg[(n & (n - 1)) * 32];
            tg[n * 32] = make_float2(prev.x + wa[b], prev.y + wb[b]);
        }
    }
    // ---- stage W1 transposed ----
    {
        float2* w1t = (float2*)(base + OFF_W1T);
        for (int idx = tid; idx < SEQ * 32; idx += NTHR) {
            int k = idx >> 5, l = idx & 31;
            w1t[k * 32 + l] =
                make_float2(W1[l * SEQ + k], W1[(l + 32) * SEQ + k]);
        }
    }
    __syncthreads();

    // per-lane constants
    const float b1_0 = b1[lane], b1_1 = b1[lane + 32];
    const float b2_0 = b2[lane], b2_1 = b2[lane + 32];
    const int   a3 = lane & 3;             // action owned by this lane
    const float b3me = b3[a3];
    const bool  lb0 = (lane & 1) != 0, lb1 = (lane & 2) != 0;
    const int w30q0 = __float2int_rn(W3[0 * HID + lane]      * W3_SCALE);
    const int w30q1 = __float2int_rn(W3[0 * HID + lane + 32] * W3_SCALE);
    const int w31q0 = __float2int_rn(W3[1 * HID + lane]      * W3_SCALE);
    const int w31q1 = __float2int_rn(W3[1 * HID + lane + 32] * W3_SCALE);
    const int w32q0 = __float2int_rn(W3[2 * HID + lane]      * W3_SCALE);
    const int w32q1 = __float2int_rn(W3[2 * HID + lane + 32] * W3_SCALE);
    const int w33q0 = __float2int_rn(W3[3 * HID + lane]      * W3_SCALE);
    const int w33q1 = __float2int_rn(W3[3 * HID + lane + 32] * W3_SCALE);

    const unsigned tb_lane = ab + (unsigned)lane * 8u;  // bits [13:8] = 0

    unsigned long long b2p;
    asm("mov.b64 %0, {%1, %2};" : "=l"(b2p) : "f"(b2_0), "f"(b2_1));

    // spike counters (register-resident nibbles; <=10 per flush segment)
    unsigned c00 = 0u, c01 = 0u;   // s2 neuron l: t 0-7, t 8-15
    unsigned c10 = 0u, c11 = 0u;   // s2 neuron l+32
    unsigned cme_lo = 0u, cme_hi = 0u;  // s3 counts for action a3

    const int gwarp = blockIdx.x * WPB + warp;
    const int row0  = gwarp * 18 + min(gwarp, WARPS_BIG);
    const int nrows = 18 + (gwarp < WARPS_BIG ? 1 : 0);

    const float2* w1t = (const float2*)(base + OFF_W1T);
    unsigned* bank2 = (unsigned*)(base + OFF_BANK2);
    unsigned* bank3 = (unsigned*)(base + OFF_BANK3);
    int seg = 0;

    for (int r = 0; r < nrows; r++) {
        const int row = row0 + r;

        // ---- cur1 = x[row] @ W1^T + b1 (coalesced + shfl broadcast) ----
        const float* xr = x + row * SEQ;
        float xown = (lane < SEQ) ? xr[lane] : 0.0f;
        float cur0 = b1_0, cur1v = b1_1;
        #pragma unroll
        for (int k = 0; k < SEQ; k++) {
            float xv = __shfl_sync(0xffffffffu, xown, k);
            float2 w = w1t[k * 32 + lane];
            cur0  = fmaf(xv, w.x, cur0);
            cur1v = fmaf(xv, w.y, cur1v);
        }

        // ---- PHASE 1: layer 1 is autonomous -> all 16 mask pairs upfront ----
        unsigned ma[TSTEP], mb[TSTEP];
        {
            float m1_0 = 0.f, m1_1 = 0.f;
            #pragma unroll
            for (int t = 0; t < TSTEP; t++) {
                m1_0 = fmaf(BETA, m1_0, cur0);
                m1_1 = fmaf(BETA, m1_1, cur1v);
                bool f0 = m1_0 > THRV, f1 = m1_1 > THRV;
                if (f0) m1_0 -= THRV;
                if (f1) m1_1 -= THRV;
                ma[t] = __ballot_sync(0xffffffffu, f0);  // neurons 0..31
                mb[t] = __ballot_sync(0xffffffffu, f1);  // neurons 32..63
            }
        }

        // ---- PHASE 2: m2/m3 recurrence; lookup streams pipeline freely ----
        float m2_0 = 0.f, m2_1 = 0.f, m3me = 0.f, acme = 0.f;

        #pragma unroll
        for (int t = 0; t < TSTEP; t++) {
            // layer 2: 11 LUT lookups (SHF + LOP3 + LDS + FADD2 each)
            unsigned long long a01 = b2p, aA = 0, aB = 0, aC = 0;
            lutW2<0 * 16384, 0x3F00u>(ma[t] << 8,                         tb_lane, a01);
            lutW2<1 * 16384, 0x3F00u>(ma[t] << 2,                         tb_lane, aA);
            lutW2<2 * 16384, 0x3F00u>(ma[t] >> 4,                         tb_lane, aB);
            lutW2<3 * 16384, 0x3F00u>(ma[t] >> 10,                        tb_lane, aC);
            lutW2<4 * 16384, 0x3F00u>(ma[t] >> 16,                        tb_lane, a01);
            lutW2<5 * 16384, 0x3F00u>(__funnelshift_r(ma[t], mb[t], 22),  tb_lane, aA);
            lutW2<6 * 16384, 0x3F00u>(mb[t] << 4,                         tb_lane, aB);
            lutW2<7 * 16384, 0x3F00u>(mb[t] >> 2,                         tb_lane, aC);
            lutW2<8 * 16384, 0x3F00u>(mb[t] >> 8,                         tb_lane, a01);
            lutW2<9 * 16384, 0x3F00u>(mb[t] >> 14,                        tb_lane, aA);
            lutW2<OFF_TBL4,  0x0F00u>(mb[t] >> 20,                        tb_lane, aB);
            asm("add.rn.f32x2 %0, %0, %1;" : "+l"(a01) : "l"(aA));
            asm("add.rn.f32x2 %0, %0, %1;" : "+l"(aB)  : "l"(aC));
            asm("add.rn.f32x2 %0, %0, %1;" : "+l"(a01) : "l"(aB));
            float a0, a1;
            asm("mov.b64 {%0, %1}, %2;" : "=f"(a0), "=f"(a1) : "l"(a01));

            m2_0 = fmaf(BETA, m2_0, a0);
            m2_1 = fmaf(BETA, m2_1, a1);
            bool q0 = m2_0 > THRV, q1 = m2_1 > THRV;
            if (q0) m2_0 -= THRV;
            if (q1) m2_1 -= THRV;

            // s2 nibble counters (t immediate under full unroll)
            unsigned nib = 1u << ((t & 7) * 4);
            if (t < 8) { c00 += q0 ? nib : 0u; c10 += q1 ? nib : 0u; }
            else       { c01 += q0 ? nib : 0u; c11 += q1 ? nib : 0u; }

            // layer 3: exact integer IMAD partials + 4 warp reduxes
            int s0i = q0 ? 1 : 0, s1i = q1 ? 1 : 0;
            int p0i = s0i * w30q0 + s1i * w30q1;
            int p1i = s0i * w31q0 + s1i * w31q1;
            int p2i = s0i * w32q0 + s1i * w32q1;
            int p3i = s0i * w33q0 + s1i * w33q1;
            p0i = warp_redux_add_s32(p0i);
            p1i = warp_redux_add_s32(p1i);
            p2i = warp_redux_add_s32(p2i);
            p3i = warp_redux_add_s32(p3i);

            // this lane updates only its own action
            int pm = lb1 ? (lb0 ? p3i : p2i) : (lb0 ? p1i : p0i);
            float pf = fmaf((float)pm, W3_INV_SCALE, b3me);
            m3me = fmaf(BETA, m3me, pf);
            bool gme = m3me > THRV;
            if (gme) { m3me -= THRV; acme += 1.0f; }

            // s3 per-t nibble counters for this lane's action
            if (t < 8) { cme_lo += gme ? nib : 0u; }
            else       { cme_hi += gme ? nib : 0u; }
        }

        // ---- softmax(acc / T): gather 4 actions, lane 0 writes ----
        float gg0 = __shfl_sync(0xffffffffu, acme, 0);
        float gg1 = __shfl_sync(0xffffffffu, acme, 1);
        float gg2 = __shfl_sync(0xffffffffu, acme, 2);
        float gg3 = __shfl_sync(0xffffffffu, acme, 3);
        if (lane == 0) {
            const float invT = 1.0f / (float)TSTEP;
            float r0 = gg0 * invT, r1 = gg1 * invT;
            float r2 = gg2 * invT, r3 = gg3 * invT;
            float mx = fmaxf(fmaxf(r0, r1), fmaxf(r2, r3));
            float e0 = __expf(r0 - mx), e1 = __expf(r1 - mx);
            float e2 = __expf(r2 - mx), e3 = __expf(r3 - mx);
            float rs = __fdividef(1.0f, e0 + e1 + e2 + e3);
            float4 o = make_float4(e0 * rs, e1 * rs, e2 * rs, e3 * rs);
            *reinterpret_cast<float4*>(out + (size_t)row * ACT) = o;
        }

        // ---- segment flush after row 10 and at the last row (<=10/nibble) ----
        if (r == 9 || r == nrows - 1) {
            unsigned* d2 = bank2 + ((seg * WPB + warp) * 32 + lane) * 4;
            *reinterpret_cast<uint4*>(d2) = make_uint4(c00, c01, c10, c11);
            if (lane < 4) {
                unsigned* d3 = bank3 + ((seg * WPB + warp) * 4 + lane) * 2;
                d3[0] = cme_lo;
                d3[1] = cme_hi;
            }
            c00 = c01 = c10 = c11 = 0u;
            cme_lo = cme_hi = 0u;
            seg++;
        }
    }

    // ---- final sweep: sum banks -> global atomics ----
    __syncthreads();
    for (int c = tid; c < TSTEP * HID; c += NTHR) {
        int t = c >> 6, j = c & 63;
        int ln = j & 31, half = j >> 5;
        int wsel = half * 2 + (t >> 3);
        int sh = (t & 7) * 4;
        unsigned cnt = 0;
        #pragma unroll
        for (int s = 0; s < 2; s++)
            for (int w = 0; w < WPB; w++)
                cnt += (bank2[((s * WPB + w) * 32 + ln) * 4 + wsel] >> sh) & 15u;
        atomicAdd(&g_s2sum[c], (float)cnt);
    }
    if (tid < TSTEP * ACT) {
        int t = tid >> 2, a = tid & 3;
        int reg = t >> 3, sh = (t & 7) * 4;
        unsigned cnt = 0;
        #pragma unroll
        for (int s = 0; s < 2; s++)
            for (int w = 0; w < WPB; w++)
                cnt += (bank3[((s * WPB + w) * 4 + a) * 2 + reg] >> sh) & 15u;
        atomicAdd(&g_s3sum[tid], (float)cnt);
    }

    // ---- last-block: eligibility trace + reset of globals ----
    unsigned* flagp = (unsigned*)(base + OFF_FLAG);
    __threadfence();
    __syncthreads();
    if (tid == 0)
        *flagp = (atomicAdd(&g_ctr, 1u) == (unsigned)(NBLK - 1)) ? 1u : 0u;
    __syncthreads();
    if (*flagp) {
        if (tid < ACT * HID) {
            int a = tid >> 6, h = tid & 63;
            const float invB = 1.0f / (float)BSZ;
            volatile float* s3v = g_s3sum;
            volatile float* s2v = g_s2sum;
            float e = elig0[tid];
            #pragma unroll
            for (int t = 0; t < TSTEP; t++) {
                float post = s3v[t * ACT + a] * invB;
                float pre  = s2v[t * HID + h] * invB;
                e = ELIG_DECAY * e + ELIG_C * (post * pre);
            }
            out[elig_off + tid] = e;
        }
        __syncthreads();
        for (int i = tid; i < TSTEP * HID; i += NTHR) g_s2sum[i] = 0.0f;
        if (tid < TSTEP * ACT) g_s3sum[tid] = 0.0f;
        if (tid == 0) g_ctr = 0u;
    }
}

// ---------------------------------------------------------------------------
// Inputs (metadata order): x, W1, b1, W2, b2, W3, b3, elig0
// Output: probs [B,4] then elig [4,64] at the tail of out.
// ---------------------------------------------------------------------------
extern "C" void kernel_launch(void* const* d_in, const int* in_sizes, int n_in,
                              void* d_out, int out_size) {
    const float* x     = (const float*)d_in[0];
    const float* W1    = (const float*)d_in[1];
    const float* b1    = (const float*)d_in[2];
    const float* W2    = (const float*)d_in[3];
    const float* b2    = (const float*)d_in[4];
    const float* W3    = (const float*)d_in[5];
    const float* b3    = (const float*)d_in[6];
    const float* elig0 = (const float*)d_in[7];
    float* out = (float*)d_out;

    cudaFuncSetAttribute(snn_main, cudaFuncAttributeMaxDynamicSharedMemorySize,
                         SMEM_REQ);
    int elig_off = out_size - ACT * HID;
    snn_main<<<NBLK, NTHR, SMEM_REQ>>>(x, W1, b1, W2, b2, W3, b3,
                                       elig0, out, elig_off);
}